// round 9
// baseline (speedup 1.0000x reference)
#include <cuda_runtime.h>
#include <math.h>

#define NLAT 61
#define NLON 120
#define NSEG (NLAT*NLON)      // 7320
#define CCH  64
#define ATT_SCALE 0.25f       // 1/sqrt(16)
#define LNEPS 1e-6f
// worst-case padded payload entries: (61*7*120 + 61*8) * 120 < 6.21M
#define EPAY_MAX 6400000

// Scratch (allocation-free rule: __device__ globals)
__device__ float g_xt [NSEG*CCH];    // x transposed to [p][c]
__device__ float g_q  [NSEG*CCH];    // pre-scaled by ATT_SCALE
__device__ float g_kv [NSEG*2*CCH];  // interleaved: [p][0:64]=k, [p][64:128]=v
__device__ float g_att[NSEG*CCH];
__device__ int   g_row_start[NLAT+1];  // original edge-row prefix
__device__ int   g_row_lenp [NLAT];    // padded row length (multiple of 8)
__device__ int   g_row_basep[NLAT];    // padded payload prefix (entry units)
__device__ int2  g_epay[EPAY_MAX];     // (kv byte offset, quad_w bits), seg-contiguous
// transposed weights: lane-contiguous layouts
__device__ float g_wq_t[4096];
__device__ float g_wk_t[4096];
__device__ float g_wv_t[4096];
__device__ float g_wo_t[4096];
__device__ float g_w1_t[8192];      // [c*128+f]
__device__ float g_w2_t[8192];      // [f*64+c]

// ---------------------------------------------------------------------------
// Kernel 0: per-output-row edge ranges + padded payload layout.
// ---------------------------------------------------------------------------
__global__ void k_rowptr(const int* __restrict__ out_idx, int NE) {
    __shared__ int cnt[NLAT];
    int tid = threadIdx.x;
    if (tid < NLAT) cnt[tid] = 0;
    __syncthreads();
    for (int e = tid; e < NE; e += blockDim.x) {
        int row = out_idx[e * 120] / 120;
        atomicAdd(&cnt[row], 1);
    }
    __syncthreads();
    if (tid == 0) {
        int acc = 0, accp = 0;
        for (int r = 0; r < NLAT; ++r) {
            g_row_start[r] = acc; acc += cnt[r];
            int lenp = (cnt[r] + 7) & ~7;
            g_row_lenp[r]  = lenp;
            g_row_basep[r] = accp; accp += lenp * 120;
        }
        g_row_start[NLAT] = acc;
    }
}

// ---------------------------------------------------------------------------
// Kernel 0b (merged prep): blocks 0..28 transpose x -> [p][c]; block 29
// transposes weights; blocks 30..90 build the per-segment payload stream:
// for lat row ho, segment column wo, edge j: (kv_byte_off, quad_w). Rows
// padded to lenp with (0, 0.0f) -> exact zero contribution, no hot-loop
// bounds checks.
// ---------------------------------------------------------------------------
__global__ void k_prep(const float* __restrict__ x,
                       const float* __restrict__ wq, const float* __restrict__ wk,
                       const float* __restrict__ wv, const float* __restrict__ wo,
                       const float* __restrict__ w1, const float* __restrict__ w2,
                       const int* __restrict__ in_idx,
                       const float* __restrict__ quad_w) {
    int tid = threadIdx.x;
    if (blockIdx.x < 29) {
        int p = blockIdx.x * 256 + tid;
        if (p < NSEG) {
            #pragma unroll
            for (int c4 = 0; c4 < 64; c4 += 4) {
                float4 t;
                t.x = __ldcs(&x[(c4+0)*NSEG + p]);
                t.y = __ldcs(&x[(c4+1)*NSEG + p]);
                t.z = __ldcs(&x[(c4+2)*NSEG + p]);
                t.w = __ldcs(&x[(c4+3)*NSEG + p]);
                *(float4*)&g_xt[p*64 + c4] = t;
            }
        }
    } else if (blockIdx.x == 29) {
        for (int i = tid; i < 4096; i += 256) {
            int o = i >> 6, c = i & 63;
            g_wq_t[c*64+o] = wq[i];
            g_wk_t[c*64+o] = wk[i];
            g_wv_t[c*64+o] = wv[i];
            g_wo_t[c*64+o] = wo[i];
        }
        for (int i = tid; i < 8192; i += 256) {    // w1: [f][c] -> [c][f]
            int f = i >> 6, c = i & 63;
            g_w1_t[c*128+f] = w1[i];
        }
        for (int i = tid; i < 8192; i += 256) {    // w2: [c][f] -> [f][c]
            int c = i >> 7, f = i & 127;
            g_w2_t[f*64+c] = w2[i];
        }
    } else {
        int ho   = blockIdx.x - 30;
        int rs   = g_row_start[ho];
        int len  = g_row_start[ho+1] - rs;
        int lenp = g_row_lenp[ho];
        int base = g_row_basep[ho];
        for (int t = tid; t < lenp*120; t += 256) {
            int j = t / 120, wo = t - j*120;       // j-major: coalesced in_idx reads
            int2 pay;
            if (j < len) {
                int s = in_idx[(rs+j)*120 + wo];
                pay = make_int2(s * 512, __float_as_int(quad_w[s]));
            } else {
                pay = make_int2(0, 0);
            }
            g_epay[base + wo*lenp + j] = pay;
        }
    }
}

// ---------------------------------------------------------------------------
// Kernel 1: LayerNorm0 + Q/K/V. One warp per 4 positions (P=4 tiling).
// q stored pre-scaled; k/v interleaved into g_kv.
// ---------------------------------------------------------------------------
__global__ void __launch_bounds__(256) k_ln_qkv(const float* __restrict__ ln_g,
                                                const float* __restrict__ ln_b) {
    __shared__ float sH[8*4*64];   // 8 KB
    int tid = threadIdx.x, warp = tid >> 5, lane = tid & 31;
    int pbase = blockIdx.x * 32 + warp * 4;
    if (pbase >= NSEG) return;
    int c0 = 2*lane, c1 = c0 + 1;
    float* mH = sH + warp*256;

    float2 xv[4]; float s0[4];
    #pragma unroll
    for (int u = 0; u < 4; ++u) {
        xv[u] = *(const float2*)&g_xt[(pbase+u)*64 + c0];
        s0[u] = xv[u].x + xv[u].y;
    }
    #pragma unroll
    for (int off = 16; off; off >>= 1) {
        #pragma unroll
        for (int u = 0; u < 4; ++u) s0[u] += __shfl_xor_sync(0xffffffffu, s0[u], off);
    }
    float da[4], db[4], vs[4];
    #pragma unroll
    for (int u = 0; u < 4; ++u) {
        float mean = s0[u] * (1.0f/64.0f);
        da[u] = xv[u].x - mean; db[u] = xv[u].y - mean;
        vs[u] = da[u]*da[u] + db[u]*db[u];
    }
    #pragma unroll
    for (int off = 16; off; off >>= 1) {
        #pragma unroll
        for (int u = 0; u < 4; ++u) vs[u] += __shfl_xor_sync(0xffffffffu, vs[u], off);
    }
    float g0 = ln_g[c0], g1 = ln_g[c1], be0 = ln_b[c0], be1 = ln_b[c1];
    #pragma unroll
    for (int u = 0; u < 4; ++u) {
        float rstd = rsqrtf(vs[u] * (1.0f/64.0f) + LNEPS);
        mH[u*64 + c0] = da[u]*rstd*g0 + be0;
        mH[u*64 + c1] = db[u]*rstd*g1 + be1;
    }
    __syncwarp();

    float aq[4][2] = {}, ak[4][2] = {}, av[4][2] = {};
    #pragma unroll 8
    for (int c = 0; c < 64; ++c) {
        float2 wq2 = __ldg((const float2*)&g_wq_t[c*64 + c0]);
        float2 wk2 = __ldg((const float2*)&g_wk_t[c*64 + c0]);
        float2 wv2 = __ldg((const float2*)&g_wv_t[c*64 + c0]);
        #pragma unroll
        for (int u = 0; u < 4; ++u) {
            float hc = mH[u*64 + c];
            aq[u][0] = fmaf(wq2.x, hc, aq[u][0]); aq[u][1] = fmaf(wq2.y, hc, aq[u][1]);
            ak[u][0] = fmaf(wk2.x, hc, ak[u][0]); ak[u][1] = fmaf(wk2.y, hc, ak[u][1]);
            av[u][0] = fmaf(wv2.x, hc, av[u][0]); av[u][1] = fmaf(wv2.y, hc, av[u][1]);
        }
    }
    #pragma unroll
    for (int u = 0; u < 4; ++u) {
        int p = pbase + u;
        *(float2*)&g_q [p*64  + c0] =
            make_float2(aq[u][0]*ATT_SCALE, aq[u][1]*ATT_SCALE);
        *(float2*)&g_kv[p*128 + c0]      = make_float2(ak[u][0], ak[u][1]);
        *(float2*)&g_kv[p*128 + 64 + c0] = make_float2(av[u][0], av[u][1]);
    }
}

// ---------------------------------------------------------------------------
// Kernel 2: neighborhood attention. One warp per segment, FOUR edges per
// warp-instruction: quarter = lane>>3 picks the edge, l = lane&7 owns
// channels 8l..8l+7 (two float4). Head score (16 ch) completes with ONE
// shfl (xor 1). Payload stream is padded -> branch-free hot loop; padded
// entries carry qw=0 (exact zero contribution). Scores are O(few) so
// exp(s) is overflow-safe without the online max (validated rel_err 2e-7).
// ---------------------------------------------------------------------------
__global__ void __launch_bounds__(256) k_attn() {
    int b = blockIdx.x;
    int bp = (b & 1) ? (914 - (b >> 1)) : (b >> 1);   // heavy pole rows first
    int warp = threadIdx.x >> 5, lane = threadIdx.x & 31;
    int p = bp * 8 + warp;
    int ho = p / 120, wo = p - ho * 120;
    int quarter = lane >> 3;              // edge slot within group-of-4
    int l = lane & 7;                     // channel-group: channels 8l..8l+7
    int c = l * 8;

    float4 qa = *(const float4*)&g_q[p*64 + c];
    float4 qb = *(const float4*)&g_q[p*64 + c + 4];

    int lenp = g_row_lenp[ho];
    const int2* pay = &g_epay[g_row_basep[ho] + wo*lenp + quarter];

    float den = 0.f;
    float4 na = make_float4(0.f,0.f,0.f,0.f);
    float4 nb = make_float4(0.f,0.f,0.f,0.f);

    const char* kvb = (const char*)g_kv;
    int ngrp = lenp >> 2;                 // groups of 4 edges (even: lenp % 8 == 0)
    #pragma unroll 1
    for (int i = 0; i < ngrp; i += 2) {
        int2 p0 = __ldg(&pay[(i  )*4]);
        int2 p1 = __ldg(&pay[(i+1)*4]);
        const char* k0 = kvb + p0.x;
        const char* k1 = kvb + p1.x;
        float4 ka0 = *(const float4*)(k0 + c*4);
        float4 kb0 = *(const float4*)(k0 + c*4 + 16);
        float4 va0 = *(const float4*)(k0 + 256 + c*4);
        float4 vb0 = *(const float4*)(k0 + 256 + c*4 + 16);
        float4 ka1 = *(const float4*)(k1 + c*4);
        float4 kb1 = *(const float4*)(k1 + c*4 + 16);
        float4 va1 = *(const float4*)(k1 + 256 + c*4);
        float4 vb1 = *(const float4*)(k1 + 256 + c*4 + 16);

        float s0 = ka0.x*qa.x + ka0.y*qa.y + ka0.z*qa.z + ka0.w*qa.w
                 + kb0.x*qb.x + kb0.y*qb.y + kb0.z*qb.z + kb0.w*qb.w;
        float s1 = ka1.x*qa.x + ka1.y*qa.y + ka1.z*qa.z + ka1.w*qa.w
                 + kb1.x*qb.x + kb1.y*qb.y + kb1.z*qb.z + kb1.w*qb.w;
        s0 += __shfl_xor_sync(0xffffffffu, s0, 1);
        s1 += __shfl_xor_sync(0xffffffffu, s1, 1);
        float pe0 = __expf(s0) * __int_as_float(p0.y);
        float pe1 = __expf(s1) * __int_as_float(p1.y);
        den += pe0;
        na.x = fmaf(pe0, va0.x, na.x); na.y = fmaf(pe0, va0.y, na.y);
        na.z = fmaf(pe0, va0.z, na.z); na.w = fmaf(pe0, va0.w, na.w);
        nb.x = fmaf(pe0, vb0.x, nb.x); nb.y = fmaf(pe0, vb0.y, nb.y);
        nb.z = fmaf(pe0, vb0.z, nb.z); nb.w = fmaf(pe0, vb0.w, nb.w);
        den += pe1;
        na.x = fmaf(pe1, va1.x, na.x); na.y = fmaf(pe1, va1.y, na.y);
        na.z = fmaf(pe1, va1.z, na.z); na.w = fmaf(pe1, va1.w, na.w);
        nb.x = fmaf(pe1, vb1.x, nb.x); nb.y = fmaf(pe1, vb1.y, nb.y);
        nb.z = fmaf(pe1, vb1.z, nb.z); nb.w = fmaf(pe1, vb1.w, nb.w);
    }
    // reduce across the four edge quarters (same l -> same channels)
    #pragma unroll
    for (int off = 8; off <= 16; off <<= 1) {
        den  += __shfl_xor_sync(0xffffffffu, den,  off);
        na.x += __shfl_xor_sync(0xffffffffu, na.x, off);
        na.y += __shfl_xor_sync(0xffffffffu, na.y, off);
        na.z += __shfl_xor_sync(0xffffffffu, na.z, off);
        na.w += __shfl_xor_sync(0xffffffffu, na.w, off);
        nb.x += __shfl_xor_sync(0xffffffffu, nb.x, off);
        nb.y += __shfl_xor_sync(0xffffffffu, nb.y, off);
        nb.z += __shfl_xor_sync(0xffffffffu, nb.z, off);
        nb.w += __shfl_xor_sync(0xffffffffu, nb.w, off);
    }
    if (quarter == 0) {
        float inv = 1.0f / den;
        *(float4*)&g_att[p*64 + c] =
            make_float4(na.x*inv, na.y*inv, na.z*inv, na.w*inv);
        *(float4*)&g_att[p*64 + c + 4] =
            make_float4(nb.x*inv, nb.y*inv, nb.z*inv, nb.w*inv);
    }
}

// ---------------------------------------------------------------------------
// Kernel 3: fused epilogue, P=4 positions per warp, L1-resident __ldg weights.
// ---------------------------------------------------------------------------
__global__ void __launch_bounds__(256) k_epilogue(const float* __restrict__ b1,
                                                  const float* __restrict__ b2,
                                                  const float* __restrict__ ln_g,
                                                  const float* __restrict__ ln_b,
                                                  float* __restrict__ out) {
    __shared__ float sV[8*4*64];    // 8 KB
    __shared__ float sT[8*4*128];   // 16 KB
    int tid = threadIdx.x, warp = tid >> 5, lane = tid & 31;
    int pbase = blockIdx.x * 32 + warp * 4;
    if (pbase >= NSEG) return;
    int c0 = 2*lane, c1 = c0 + 1;
    float* mV = sV + warp*256;
    float* mT = sT + warp*512;

    #pragma unroll
    for (int u = 0; u < 4; ++u) {
        float2 a2 = *(const float2*)&g_att[(pbase+u)*64 + c0];
        mV[u*64 + c0] = a2.x; mV[u*64 + c1] = a2.y;
    }
    __syncwarp();

    // a = wo @ att
    float acc[4][2] = {};
    #pragma unroll 8
    for (int c = 0; c < 64; ++c) {
        float2 w = __ldg((const float2*)&g_wo_t[c*64 + c0]);
        #pragma unroll
        for (int u = 0; u < 4; ++u) {
            float hc = mV[u*64 + c];
            acc[u][0] = fmaf(w.x, hc, acc[u][0]);
            acc[u][1] = fmaf(w.y, hc, acc[u][1]);
        }
    }
    // x1 = a + x ; LN1
    float x1a[4], x1b[4], s0[4];
    #pragma unroll
    for (int u = 0; u < 4; ++u) {
        float2 xv = *(const float2*)&g_xt[(pbase+u)*64 + c0];
        x1a[u] = acc[u][0] + xv.x;
        x1b[u] = acc[u][1] + xv.y;
        s0[u] = x1a[u] + x1b[u];
    }
    #pragma unroll
    for (int off = 16; off; off >>= 1) {
        #pragma unroll
        for (int u = 0; u < 4; ++u) s0[u] += __shfl_xor_sync(0xffffffffu, s0[u], off);
    }
    float da[4], db[4], vs[4];
    #pragma unroll
    for (int u = 0; u < 4; ++u) {
        float mean = s0[u] * (1.0f/64.0f);
        da[u] = x1a[u] - mean; db[u] = x1b[u] - mean;
        vs[u] = da[u]*da[u] + db[u]*db[u];
    }
    #pragma unroll
    for (int off = 16; off; off >>= 1) {
        #pragma unroll
        for (int u = 0; u < 4; ++u) vs[u] += __shfl_xor_sync(0xffffffffu, vs[u], off);
    }
    float g0 = ln_g[c0], g1 = ln_g[c1], be0 = ln_b[c0], be1 = ln_b[c1];
    __syncwarp();   // all lanes done reading mV in the wo loop
    #pragma unroll
    for (int u = 0; u < 4; ++u) {
        float rstd = rsqrtf(vs[u] * (1.0f/64.0f) + LNEPS);
        mV[u*64 + c0] = da[u]*rstd*g0 + be0;
        mV[u*64 + c1] = db[u]*rstd*g1 + be1;
    }
    __syncwarp();

    // t = gelu(w1 @ h1 + b1)
    float t[4][4] = {};
    #pragma unroll 8
    for (int c = 0; c < 64; ++c) {
        float2 wA = __ldg((const float2*)&g_w1_t[c*128 + c0]);
        float2 wB = __ldg((const float2*)&g_w1_t[c*128 + 64 + c0]);
        #pragma unroll
        for (int u = 0; u < 4; ++u) {
            float hc = mV[u*64 + c];
            t[u][0] = fmaf(wA.x, hc, t[u][0]); t[u][1] = fmaf(wA.y, hc, t[u][1]);
            t[u][2] = fmaf(wB.x, hc, t[u][2]); t[u][3] = fmaf(wB.y, hc, t[u][3]);
        }
    }
    const float RS2 = 0.70710678118654752f;
    float bb0 = b1[c0], bb1 = b1[c1], bb2 = b1[64+c0], bb3 = b1[64+c1];
    #pragma unroll
    for (int u = 0; u < 4; ++u) {
        float v0 = t[u][0] + bb0, v1 = t[u][1] + bb1;
        float v2 = t[u][2] + bb2, v3 = t[u][3] + bb3;
        mT[u*128 + c0]      = 0.5f*v0*(1.f + erff(v0*RS2));
        mT[u*128 + c1]      = 0.5f*v1*(1.f + erff(v1*RS2));
        mT[u*128 + 64 + c0] = 0.5f*v2*(1.f + erff(v2*RS2));
        mT[u*128 + 64 + c1] = 0.5f*v3*(1.f + erff(v3*RS2));
    }
    __syncwarp();

    // out = w2 @ t + b2 + x1
    float o[4][2] = {};
    #pragma unroll 8
    for (int f = 0; f < 128; ++f) {
        float2 w = __ldg((const float2*)&g_w2_t[f*64 + c0]);
        #pragma unroll
        for (int u = 0; u < 4; ++u) {
            float tf = mT[u*128 + f];
            o[u][0] = fmaf(w.x, tf, o[u][0]);
            o[u][1] = fmaf(w.y, tf, o[u][1]);
        }
    }
    float ob0 = b2[c0], ob1 = b2[c1];
    #pragma unroll
    for (int u = 0; u < 4; ++u) {
        int p = pbase + u;
        out[c0*NSEG + p] = o[u][0] + ob0 + x1a[u];
        out[c1*NSEG + p] = o[u][1] + ob1 + x1b[u];
    }
}

// ---------------------------------------------------------------------------
// Launch. Inputs: x, wq, wk, wv, wo, w1, b1, w2, b2, ln0_g, ln0_b,
// ln1_g, ln1_b, quad_w, out_idx, in_idx.
// ---------------------------------------------------------------------------
extern "C" void kernel_launch(void* const* d_in, const int* in_sizes, int n_in,
                              void* d_out, int out_size) {
    const float* x      = (const float*)d_in[0];
    const float* wq     = (const float*)d_in[1];
    const float* wk     = (const float*)d_in[2];
    const float* wv     = (const float*)d_in[3];
    const float* wmo    = (const float*)d_in[4];
    const float* w1     = (const float*)d_in[5];
    const float* b1     = (const float*)d_in[6];
    const float* w2     = (const float*)d_in[7];
    const float* b2     = (const float*)d_in[8];
    const float* ln0_g  = (const float*)d_in[9];
    const float* ln0_b  = (const float*)d_in[10];
    const float* ln1_g  = (const float*)d_in[11];
    const float* ln1_b  = (const float*)d_in[12];
    const float* quad_w = (const float*)d_in[13];
    const int*   out_idx= (const int*)d_in[14];
    const int*   in_idx = (const int*)d_in[15];
    float* out = (float*)d_out;

    int NNZ = in_sizes[14];
    int NE  = NNZ / 120;

    k_rowptr  <<<1, 1024>>>(out_idx, NE);
    k_prep    <<<91, 256>>>(x, wq, wk, wv, wmo, w1, w2, in_idx, quad_w);
    k_ln_qkv  <<<229, 256>>>(ln0_g, ln0_b);
    k_attn    <<<915, 256>>>();
    k_epilogue<<<229, 256>>>(b1, b2, ln1_g, ln1_b, out);
}

// round 10
// speedup vs baseline: 1.2443x; 1.2443x over previous
#include <cuda_runtime.h>
#include <math.h>

#define NLAT 61
#define NLON 120
#define NSEG (NLAT*NLON)      // 7320
#define CCH  64
#define ATT_SCALE 0.25f       // 1/sqrt(16)
#define LNEPS 1e-6f
// worst-case padded payload entries: (61*7*120 + 61*8) * 120 < 6.21M
#define EPAY_MAX 6400000

// Scratch (allocation-free rule: __device__ globals)
__device__ float g_xt [NSEG*CCH];    // x transposed to [p][c]
__device__ float g_q  [NSEG*CCH];    // pre-scaled by ATT_SCALE
__device__ float g_kv [NSEG*2*CCH];  // interleaved: [p][0:64]=k, [p][64:128]=v
__device__ float g_att[NSEG*CCH];
__device__ int   g_row_start[NLAT+1];  // original edge-row prefix
__device__ int   g_row_lenp [NLAT];    // padded row length (multiple of 8)
__device__ int   g_row_basep[NLAT];    // padded payload prefix (entry units)
__device__ int2  g_epay[EPAY_MAX];     // (kv byte offset, quad_w bits), seg-contiguous
// transposed weights: lane-contiguous layouts
__device__ float g_wq_t[4096];
__device__ float g_wk_t[4096];
__device__ float g_wv_t[4096];
__device__ float g_wo_t[4096];
__device__ float g_w1_t[8192];      // [c*128+f]
__device__ float g_w2_t[8192];      // [f*64+c]

// ---------------------------------------------------------------------------
// Kernel 0: per-output-row edge ranges + padded payload layout.
// ---------------------------------------------------------------------------
__global__ void k_rowptr(const int* __restrict__ out_idx, int NE) {
    __shared__ int cnt[NLAT];
    int tid = threadIdx.x;
    if (tid < NLAT) cnt[tid] = 0;
    __syncthreads();
    for (int e = tid; e < NE; e += blockDim.x) {
        int row = out_idx[e * 120] / 120;
        atomicAdd(&cnt[row], 1);
    }
    __syncthreads();
    if (tid == 0) {
        int acc = 0, accp = 0;
        for (int r = 0; r < NLAT; ++r) {
            g_row_start[r] = acc; acc += cnt[r];
            int lenp = (cnt[r] + 7) & ~7;
            g_row_lenp[r]  = lenp;
            g_row_basep[r] = accp; accp += lenp * 120;
        }
        g_row_start[NLAT] = acc;
    }
}

// ---------------------------------------------------------------------------
// Kernel 0b: transpose x -> [p][c]; weights -> lane-contiguous layouts.
// ---------------------------------------------------------------------------
__global__ void k_prep(const float* __restrict__ x,
                       const float* __restrict__ wq, const float* __restrict__ wk,
                       const float* __restrict__ wv, const float* __restrict__ wo,
                       const float* __restrict__ w1, const float* __restrict__ w2) {
    int tid = threadIdx.x;
    if (blockIdx.x < 29) {
        int p = blockIdx.x * 256 + tid;
        if (p < NSEG) {
            #pragma unroll
            for (int c4 = 0; c4 < 64; c4 += 4) {
                float4 t;
                t.x = __ldcs(&x[(c4+0)*NSEG + p]);
                t.y = __ldcs(&x[(c4+1)*NSEG + p]);
                t.z = __ldcs(&x[(c4+2)*NSEG + p]);
                t.w = __ldcs(&x[(c4+3)*NSEG + p]);
                *(float4*)&g_xt[p*64 + c4] = t;
            }
        }
    } else {
        for (int i = tid; i < 4096; i += 256) {
            int o = i >> 6, c = i & 63;
            g_wq_t[c*64+o] = wq[i];
            g_wk_t[c*64+o] = wk[i];
            g_wv_t[c*64+o] = wv[i];
            g_wo_t[c*64+o] = wo[i];
        }
        for (int i = tid; i < 8192; i += 256) {    // w1: [f][c] -> [c][f]
            int f = i >> 6, c = i & 63;
            g_w1_t[c*128+f] = w1[i];
        }
        for (int i = tid; i < 8192; i += 256) {    // w2: [c][f] -> [f][c]
            int c = i >> 7, f = i & 127;
            g_w2_t[f*64+c] = w2[i];
        }
    }
}

// ---------------------------------------------------------------------------
// Kernel 0c: payload build, massively parallel (61 x 15 blocks). Row ho,
// segment column wo, edge j: (kv_byte_off, quad_w bits). Rows padded to
// lenp with (0, 0.0f) -> exact zero contribution, branch-free hot loop.
// ---------------------------------------------------------------------------
__global__ void __launch_bounds__(256) k_pay(const int* __restrict__ in_idx,
                                             const float* __restrict__ quad_w) {
    int ho   = blockIdx.x;
    int rs   = g_row_start[ho];
    int len  = g_row_start[ho+1] - rs;
    int lenp = g_row_lenp[ho];
    int base = g_row_basep[ho];
    int tot  = lenp * 120;
    #pragma unroll 2
    for (int t = blockIdx.y * 256 + threadIdx.x; t < tot; t += gridDim.y * 256) {
        int j = t / 120, wo = t - j*120;           // j-major: coalesced in_idx reads
        int2 pay = make_int2(0, 0);
        if (j < len) {
            int s = __ldg(&in_idx[(rs+j)*120 + wo]);
            pay = make_int2(s * 512, __float_as_int(__ldg(&quad_w[s])));
        }
        g_epay[base + wo*lenp + j] = pay;
    }
}

// ---------------------------------------------------------------------------
// Kernel 1: LayerNorm0 + Q/K/V. One warp per 4 positions (P=4 tiling).
// q stored pre-scaled; k/v interleaved into g_kv.
// ---------------------------------------------------------------------------
__global__ void __launch_bounds__(256) k_ln_qkv(const float* __restrict__ ln_g,
                                                const float* __restrict__ ln_b) {
    __shared__ float sH[8*4*64];   // 8 KB
    int tid = threadIdx.x, warp = tid >> 5, lane = tid & 31;
    int pbase = blockIdx.x * 32 + warp * 4;
    if (pbase >= NSEG) return;
    int c0 = 2*lane, c1 = c0 + 1;
    float* mH = sH + warp*256;

    float2 xv[4]; float s0[4];
    #pragma unroll
    for (int u = 0; u < 4; ++u) {
        xv[u] = *(const float2*)&g_xt[(pbase+u)*64 + c0];
        s0[u] = xv[u].x + xv[u].y;
    }
    #pragma unroll
    for (int off = 16; off; off >>= 1) {
        #pragma unroll
        for (int u = 0; u < 4; ++u) s0[u] += __shfl_xor_sync(0xffffffffu, s0[u], off);
    }
    float da[4], db[4], vs[4];
    #pragma unroll
    for (int u = 0; u < 4; ++u) {
        float mean = s0[u] * (1.0f/64.0f);
        da[u] = xv[u].x - mean; db[u] = xv[u].y - mean;
        vs[u] = da[u]*da[u] + db[u]*db[u];
    }
    #pragma unroll
    for (int off = 16; off; off >>= 1) {
        #pragma unroll
        for (int u = 0; u < 4; ++u) vs[u] += __shfl_xor_sync(0xffffffffu, vs[u], off);
    }
    float g0 = ln_g[c0], g1 = ln_g[c1], be0 = ln_b[c0], be1 = ln_b[c1];
    #pragma unroll
    for (int u = 0; u < 4; ++u) {
        float rstd = rsqrtf(vs[u] * (1.0f/64.0f) + LNEPS);
        mH[u*64 + c0] = da[u]*rstd*g0 + be0;
        mH[u*64 + c1] = db[u]*rstd*g1 + be1;
    }
    __syncwarp();

    float aq[4][2] = {}, ak[4][2] = {}, av[4][2] = {};
    #pragma unroll 8
    for (int c = 0; c < 64; ++c) {
        float2 wq2 = __ldg((const float2*)&g_wq_t[c*64 + c0]);
        float2 wk2 = __ldg((const float2*)&g_wk_t[c*64 + c0]);
        float2 wv2 = __ldg((const float2*)&g_wv_t[c*64 + c0]);
        #pragma unroll
        for (int u = 0; u < 4; ++u) {
            float hc = mH[u*64 + c];
            aq[u][0] = fmaf(wq2.x, hc, aq[u][0]); aq[u][1] = fmaf(wq2.y, hc, aq[u][1]);
            ak[u][0] = fmaf(wk2.x, hc, ak[u][0]); ak[u][1] = fmaf(wk2.y, hc, ak[u][1]);
            av[u][0] = fmaf(wv2.x, hc, av[u][0]); av[u][1] = fmaf(wv2.y, hc, av[u][1]);
        }
    }
    #pragma unroll
    for (int u = 0; u < 4; ++u) {
        int p = pbase + u;
        *(float2*)&g_q [p*64  + c0] =
            make_float2(aq[u][0]*ATT_SCALE, aq[u][1]*ATT_SCALE);
        *(float2*)&g_kv[p*128 + c0]      = make_float2(ak[u][0], ak[u][1]);
        *(float2*)&g_kv[p*128 + 64 + c0] = make_float2(av[u][0], av[u][1]);
    }
}

// ---------------------------------------------------------------------------
// Kernel 2: neighborhood attention. One warp per segment, 4 edges per
// warp-instruction (quarter = lane>>3). Lane l owns channels {4l..4l+3}
// (heads 0/1) and {32+4l..32+4l+3} (heads 2/3): every LDG.128 is 128B
// contiguous per row -> 1 line/row = 4 wavefronts (the line floor), vs 8
// with the 8-contiguous mapping. Two per-half scores, each reduced with
// 2 shfls over the 4-lane head group. Padded entries carry qw=0.
// ---------------------------------------------------------------------------
__global__ void __launch_bounds__(256) k_attn() {
    int b = blockIdx.x;
    int bp = (b & 1) ? (914 - (b >> 1)) : (b >> 1);   // heavy pole rows first
    int warp = threadIdx.x >> 5, lane = threadIdx.x & 31;
    int p = bp * 8 + warp;
    int ho = p / 120, wo = p - ho * 120;
    int quarter = lane >> 3;              // edge slot within group-of-4
    int l = lane & 7;
    int ca = 4*l;                         // head l>>2     (0 or 1)
    int cb = 32 + 4*l;                    // head 2+(l>>2) (2 or 3)

    float4 qa = *(const float4*)&g_q[p*64 + ca];
    float4 qb = *(const float4*)&g_q[p*64 + cb];

    int lenp = g_row_lenp[ho];
    const int2* pay = &g_epay[g_row_basep[ho] + wo*lenp + quarter];

    float dena = 0.f, denb = 0.f;
    float4 na = make_float4(0.f,0.f,0.f,0.f);
    float4 nb = make_float4(0.f,0.f,0.f,0.f);

    const char* kvb = (const char*)g_kv;
    int ngrp = lenp >> 2;                 // groups of 4 edges (lenp % 8 == 0)
    #pragma unroll 1
    for (int i = 0; i < ngrp; i += 2) {
        int2 p0 = __ldg(&pay[(i  )*4]);
        int2 p1 = __ldg(&pay[(i+1)*4]);
        const char* k0 = kvb + p0.x;
        const char* k1 = kvb + p1.x;
        float4 ka0 = *(const float4*)(k0 + ca*4);
        float4 kb0 = *(const float4*)(k0 + cb*4);
        float4 va0 = *(const float4*)(k0 + 256 + ca*4);
        float4 vb0 = *(const float4*)(k0 + 256 + cb*4);
        float4 ka1 = *(const float4*)(k1 + ca*4);
        float4 kb1 = *(const float4*)(k1 + cb*4);
        float4 va1 = *(const float4*)(k1 + 256 + ca*4);
        float4 vb1 = *(const float4*)(k1 + 256 + cb*4);

        float sa0 = ka0.x*qa.x + ka0.y*qa.y + ka0.z*qa.z + ka0.w*qa.w;
        float sb0 = kb0.x*qb.x + kb0.y*qb.y + kb0.z*qb.z + kb0.w*qb.w;
        float sa1 = ka1.x*qa.x + ka1.y*qa.y + ka1.z*qa.z + ka1.w*qa.w;
        float sb1 = kb1.x*qb.x + kb1.y*qb.y + kb1.z*qb.z + kb1.w*qb.w;
        sa0 += __shfl_xor_sync(0xffffffffu, sa0, 1);
        sb0 += __shfl_xor_sync(0xffffffffu, sb0, 1);
        sa1 += __shfl_xor_sync(0xffffffffu, sa1, 1);
        sb1 += __shfl_xor_sync(0xffffffffu, sb1, 1);
        sa0 += __shfl_xor_sync(0xffffffffu, sa0, 2);
        sb0 += __shfl_xor_sync(0xffffffffu, sb0, 2);
        sa1 += __shfl_xor_sync(0xffffffffu, sa1, 2);
        sb1 += __shfl_xor_sync(0xffffffffu, sb1, 2);
        float w0 = __int_as_float(p0.y);
        float w1 = __int_as_float(p1.y);
        float pa0 = __expf(sa0) * w0, pb0 = __expf(sb0) * w0;
        float pa1 = __expf(sa1) * w1, pb1 = __expf(sb1) * w1;
        dena += pa0; denb += pb0;
        na.x = fmaf(pa0, va0.x, na.x); na.y = fmaf(pa0, va0.y, na.y);
        na.z = fmaf(pa0, va0.z, na.z); na.w = fmaf(pa0, va0.w, na.w);
        nb.x = fmaf(pb0, vb0.x, nb.x); nb.y = fmaf(pb0, vb0.y, nb.y);
        nb.z = fmaf(pb0, vb0.z, nb.z); nb.w = fmaf(pb0, vb0.w, nb.w);
        dena += pa1; denb += pb1;
        na.x = fmaf(pa1, va1.x, na.x); na.y = fmaf(pa1, va1.y, na.y);
        na.z = fmaf(pa1, va1.z, na.z); na.w = fmaf(pa1, va1.w, na.w);
        nb.x = fmaf(pb1, vb1.x, nb.x); nb.y = fmaf(pb1, vb1.y, nb.y);
        nb.z = fmaf(pb1, vb1.z, nb.z); nb.w = fmaf(pb1, vb1.w, nb.w);
    }
    // reduce across the four edge quarters (same l -> same channels)
    #pragma unroll
    for (int off = 8; off <= 16; off <<= 1) {
        dena += __shfl_xor_sync(0xffffffffu, dena, off);
        denb += __shfl_xor_sync(0xffffffffu, denb, off);
        na.x += __shfl_xor_sync(0xffffffffu, na.x, off);
        na.y += __shfl_xor_sync(0xffffffffu, na.y, off);
        na.z += __shfl_xor_sync(0xffffffffu, na.z, off);
        na.w += __shfl_xor_sync(0xffffffffu, na.w, off);
        nb.x += __shfl_xor_sync(0xffffffffu, nb.x, off);
        nb.y += __shfl_xor_sync(0xffffffffu, nb.y, off);
        nb.z += __shfl_xor_sync(0xffffffffu, nb.z, off);
        nb.w += __shfl_xor_sync(0xffffffffu, nb.w, off);
    }
    if (quarter == 0) {
        float inva = 1.0f / dena;
        float invb = 1.0f / denb;
        *(float4*)&g_att[p*64 + ca] =
            make_float4(na.x*inva, na.y*inva, na.z*inva, na.w*inva);
        *(float4*)&g_att[p*64 + cb] =
            make_float4(nb.x*invb, nb.y*invb, nb.z*invb, nb.w*invb);
    }
}

// ---------------------------------------------------------------------------
// Kernel 3: fused epilogue, P=4 positions per warp, L1-resident __ldg weights.
// ---------------------------------------------------------------------------
__global__ void __launch_bounds__(256) k_epilogue(const float* __restrict__ b1,
                                                  const float* __restrict__ b2,
                                                  const float* __restrict__ ln_g,
                                                  const float* __restrict__ ln_b,
                                                  float* __restrict__ out) {
    __shared__ float sV[8*4*64];    // 8 KB
    __shared__ float sT[8*4*128];   // 16 KB
    int tid = threadIdx.x, warp = tid >> 5, lane = tid & 31;
    int pbase = blockIdx.x * 32 + warp * 4;
    if (pbase >= NSEG) return;
    int c0 = 2*lane, c1 = c0 + 1;
    float* mV = sV + warp*256;
    float* mT = sT + warp*512;

    #pragma unroll
    for (int u = 0; u < 4; ++u) {
        float2 a2 = *(const float2*)&g_att[(pbase+u)*64 + c0];
        mV[u*64 + c0] = a2.x; mV[u*64 + c1] = a2.y;
    }
    __syncwarp();

    // a = wo @ att
    float acc[4][2] = {};
    #pragma unroll 8
    for (int c = 0; c < 64; ++c) {
        float2 w = __ldg((const float2*)&g_wo_t[c*64 + c0]);
        #pragma unroll
        for (int u = 0; u < 4; ++u) {
            float hc = mV[u*64 + c];
            acc[u][0] = fmaf(w.x, hc, acc[u][0]);
            acc[u][1] = fmaf(w.y, hc, acc[u][1]);
        }
    }
    // x1 = a + x ; LN1
    float x1a[4], x1b[4], s0[4];
    #pragma unroll
    for (int u = 0; u < 4; ++u) {
        float2 xv = *(const float2*)&g_xt[(pbase+u)*64 + c0];
        x1a[u] = acc[u][0] + xv.x;
        x1b[u] = acc[u][1] + xv.y;
        s0[u] = x1a[u] + x1b[u];
    }
    #pragma unroll
    for (int off = 16; off; off >>= 1) {
        #pragma unroll
        for (int u = 0; u < 4; ++u) s0[u] += __shfl_xor_sync(0xffffffffu, s0[u], off);
    }
    float da[4], db[4], vs[4];
    #pragma unroll
    for (int u = 0; u < 4; ++u) {
        float mean = s0[u] * (1.0f/64.0f);
        da[u] = x1a[u] - mean; db[u] = x1b[u] - mean;
        vs[u] = da[u]*da[u] + db[u]*db[u];
    }
    #pragma unroll
    for (int off = 16; off; off >>= 1) {
        #pragma unroll
        for (int u = 0; u < 4; ++u) vs[u] += __shfl_xor_sync(0xffffffffu, vs[u], off);
    }
    float g0 = ln_g[c0], g1 = ln_g[c1], be0 = ln_b[c0], be1 = ln_b[c1];
    __syncwarp();   // all lanes done reading mV in the wo loop
    #pragma unroll
    for (int u = 0; u < 4; ++u) {
        float rstd = rsqrtf(vs[u] * (1.0f/64.0f) + LNEPS);
        mV[u*64 + c0] = da[u]*rstd*g0 + be0;
        mV[u*64 + c1] = db[u]*rstd*g1 + be1;
    }
    __syncwarp();

    // t = gelu(w1 @ h1 + b1)
    float t[4][4] = {};
    #pragma unroll 8
    for (int c = 0; c < 64; ++c) {
        float2 wA = __ldg((const float2*)&g_w1_t[c*128 + c0]);
        float2 wB = __ldg((const float2*)&g_w1_t[c*128 + 64 + c0]);
        #pragma unroll
        for (int u = 0; u < 4; ++u) {
            float hc = mV[u*64 + c];
            t[u][0] = fmaf(wA.x, hc, t[u][0]); t[u][1] = fmaf(wA.y, hc, t[u][1]);
            t[u][2] = fmaf(wB.x, hc, t[u][2]); t[u][3] = fmaf(wB.y, hc, t[u][3]);
        }
    }
    const float RS2 = 0.70710678118654752f;
    float bb0 = b1[c0], bb1 = b1[c1], bb2 = b1[64+c0], bb3 = b1[64+c1];
    #pragma unroll
    for (int u = 0; u < 4; ++u) {
        float v0 = t[u][0] + bb0, v1 = t[u][1] + bb1;
        float v2 = t[u][2] + bb2, v3 = t[u][3] + bb3;
        mT[u*128 + c0]      = 0.5f*v0*(1.f + erff(v0*RS2));
        mT[u*128 + c1]      = 0.5f*v1*(1.f + erff(v1*RS2));
        mT[u*128 + 64 + c0] = 0.5f*v2*(1.f + erff(v2*RS2));
        mT[u*128 + 64 + c1] = 0.5f*v3*(1.f + erff(v3*RS2));
    }
    __syncwarp();

    // out = w2 @ t + b2 + x1
    float o[4][2] = {};
    #pragma unroll 8
    for (int f = 0; f < 128; ++f) {
        float2 w = __ldg((const float2*)&g_w2_t[f*64 + c0]);
        #pragma unroll
        for (int u = 0; u < 4; ++u) {
            float tf = mT[u*128 + f];
            o[u][0] = fmaf(w.x, tf, o[u][0]);
            o[u][1] = fmaf(w.y, tf, o[u][1]);
        }
    }
    float ob0 = b2[c0], ob1 = b2[c1];
    #pragma unroll
    for (int u = 0; u < 4; ++u) {
        int p = pbase + u;
        out[c0*NSEG + p] = o[u][0] + ob0 + x1a[u];
        out[c1*NSEG + p] = o[u][1] + ob1 + x1b[u];
    }
}

// ---------------------------------------------------------------------------
// Launch. Inputs: x, wq, wk, wv, wo, w1, b1, w2, b2, ln0_g, ln0_b,
// ln1_g, ln1_b, quad_w, out_idx, in_idx.
// ---------------------------------------------------------------------------
extern "C" void kernel_launch(void* const* d_in, const int* in_sizes, int n_in,
                              void* d_out, int out_size) {
    const float* x      = (const float*)d_in[0];
    const float* wq     = (const float*)d_in[1];
    const float* wk     = (const float*)d_in[2];
    const float* wv     = (const float*)d_in[3];
    const float* wmo    = (const float*)d_in[4];
    const float* w1     = (const float*)d_in[5];
    const float* b1     = (const float*)d_in[6];
    const float* w2     = (const float*)d_in[7];
    const float* b2     = (const float*)d_in[8];
    const float* ln0_g  = (const float*)d_in[9];
    const float* ln0_b  = (const float*)d_in[10];
    const float* ln1_g  = (const float*)d_in[11];
    const float* ln1_b  = (const float*)d_in[12];
    const float* quad_w = (const float*)d_in[13];
    const int*   out_idx= (const int*)d_in[14];
    const int*   in_idx = (const int*)d_in[15];
    float* out = (float*)d_out;

    int NNZ = in_sizes[14];
    int NE  = NNZ / 120;

    k_rowptr  <<<1, 1024>>>(out_idx, NE);
    k_prep    <<<30, 256>>>(x, wq, wk, wv, wmo, w1, w2);
    k_pay     <<<dim3(61, 15), 256>>>(in_idx, quad_w);
    k_ln_qkv  <<<229, 256>>>(ln0_g, ln0_b);
    k_attn    <<<915, 256>>>();
    k_epilogue<<<229, 256>>>(b1, b2, ln1_g, ln1_b, out);
}